// round 6
// baseline (speedup 1.0000x reference)
#include <cuda_runtime.h>
#include <cuda_bf16.h>
#include <math.h>

#define D 128
#define QVS 256                   // qv row stride (q at 0..127, v at 128..255)
#define MAXN 50000
#define MAXE 600000

// ---------------- scratch (static device globals; no allocation) ----------------
__device__ float          g_yu[MAXN * D];
__device__ float          g_yi[MAXN * D];
__device__ __nv_bfloat16  g_agg[2][MAXN * D];        // 0: items (ui pass), 1: users (iu pass)
__device__ __nv_bfloat16  g_xbu[MAXN * D];
__device__ __nv_bfloat16  g_xbi[MAXN * D];
__device__ __nv_bfloat16  g_qv[2][MAXN * QVS];       // interleaved q|v per pass
__device__ __nv_bfloat16  g_k[2][MAXN * D];
__device__ __nv_bfloat16  g_Mtb[4][D * D];           // 4 = 2 layers x 2 passes
__device__ __nv_bfloat16  g_Kb[4][D * D];
__device__ __nv_bfloat16  g_Vb[4][D * D];
__device__ float          g_cb[4][D];
__device__ float          g_sum[4];
__device__ int            g_deg[2][MAXN];
__device__ int            g_cur[2][MAXN];
__device__ int            g_off_ui[MAXN + 1];
__device__ int            g_off_iu[MAXN + 1];
__device__ int            g_src_ui[MAXE];
__device__ int            g_src_iu[MAXE];

// ---------------- all-layer weight prep (4 passes: layer*2 + edgetype) ----------------
struct PrepBatch {
    const float* qw[4]; const float* qb[4]; const float* W[4];
    const float* kw[4]; const float* vw[4];
    __nv_bfloat16* Mtb; __nv_bfloat16* Kb; __nv_bfloat16* Vb;
    float* cb; float* psum;
};

__global__ void prep_batch(PrepBatch pb)
{
    const int p  = blockIdx.y;
    const int bx = blockIdx.x;
    if (bx == 0 && threadIdx.x == 0) pb.psum[p] = 0.f;
    if (bx < 65) {
        int id = bx * 256 + threadIdx.x;
        if (id < D * D) {
            int j = id / D, d = id % D;
            const float* qw = pb.qw[p];
            const float* W  = pb.W[p];
            float s = 0.f;
            #pragma unroll 8
            for (int e = 0; e < D; ++e) s = fmaf(qw[e * D + d], W[e * D + j], s);
            pb.Mtb[p * D * D + j * D + d] = __float2bfloat16(s);
        } else if (id < D * D + D) {
            int j = id - D * D;
            const float* qb = pb.qb[p];
            const float* W  = pb.W[p];
            float s = 0.f;
            #pragma unroll 8
            for (int e = 0; e < D; ++e) s = fmaf(qb[e], W[e * D + j], s);
            pb.cb[p * D + j] = s;
        }
    } else if (bx < 129) {
        int id = (bx - 65) * 256 + threadIdx.x;
        pb.Kb[p * D * D + id] = __float2bfloat16(pb.kw[p][id]);
    } else {
        int id = (bx - 129) * 256 + threadIdx.x;
        pb.Vb[p * D * D + id] = __float2bfloat16(pb.vw[p][id]);
    }
}

// ---------------- batched fp32 -> bf16 convert ----------------
struct ConvB { const float* x[2]; __nv_bfloat16* y[2]; int n4[2]; };

__global__ void conv_b16(ConvB cv)
{
    const int t = blockIdx.y;
    int i = blockIdx.x * blockDim.x + threadIdx.x;
    if (i >= cv.n4[t]) return;
    float4 v = ((const float4*)cv.x[t])[i];
    __nv_bfloat162 lo = __floats2bfloat162_rn(v.x, v.y);
    __nv_bfloat162 hi = __floats2bfloat162_rn(v.z, v.w);
    uint2 o;
    o.x = *(unsigned int*)&lo;
    o.y = *(unsigned int*)&hi;
    ((uint2*)cv.y[t])[i] = o;
}

// ---------------- bf16 tensor-core batched GEMM: C[N,128] = bf16(X @ Wm^T + bias) ----------------
__device__ __forceinline__ void mma16816(float c[4],
                                         unsigned a0, unsigned a1, unsigned a2, unsigned a3,
                                         unsigned b0, unsigned b1)
{
    asm volatile("mma.sync.aligned.m16n8k16.row.col.f32.bf16.bf16.f32 "
                 "{%0,%1,%2,%3}, {%4,%5,%6,%7}, {%8,%9}, {%0,%1,%2,%3};"
                 : "+f"(c[0]), "+f"(c[1]), "+f"(c[2]), "+f"(c[3])
                 : "r"(a0), "r"(a1), "r"(a2), "r"(a3), "r"(b0), "r"(b1));
}

#define GSTRIDE 136   // smem row stride in bf16 elems; 68 words, 68 mod 32 = 4 -> conflict-free

struct GemmBatch {
    const __nv_bfloat16* X[6];
    const __nv_bfloat16* W[6];
    const float*         bias[6];
    __nv_bfloat16*       C[6];
    int                  N[6];
    int                  cs[6];     // output row stride
};

__global__ __launch_bounds__(256, 2) void gemm_batch(GemmBatch gb)
{
    extern __shared__ __nv_bfloat16 sh[];
    __nv_bfloat16* Xs = sh;                   // [128][GSTRIDE]
    __nv_bfloat16* Ws = sh + 128 * GSTRIDE;   // [128][GSTRIDE]
    const int g = blockIdx.y;
    const int N = gb.N[g];
    const int row0 = blockIdx.x * 128;
    if (row0 >= N) return;
    const __nv_bfloat16* __restrict__ X  = gb.X[g];
    const __nv_bfloat16* __restrict__ Wm = gb.W[g];
    const float* __restrict__ bias       = gb.bias[g];
    __nv_bfloat16* __restrict__ C        = gb.C[g];
    const int cs = gb.cs[g];

    const int tid  = threadIdx.x;
    const int warp = tid >> 5, lane = tid & 31;

    #pragma unroll
    for (int i = 0; i < 8; ++i) {
        int seg = tid + i * 256;
        int r = seg >> 4, c = (seg & 15) << 3;
        *(uint4*)(Ws + r * GSTRIDE + c) = *(const uint4*)(Wm + r * D + c);
    }
    #pragma unroll
    for (int i = 0; i < 8; ++i) {
        int seg = tid + i * 256;
        int r = seg >> 4, c = (seg & 15) << 3;
        int gr = row0 + r;
        uint4 val = make_uint4(0u, 0u, 0u, 0u);
        if (gr < N) val = *(const uint4*)(X + (size_t)gr * D + c);
        *(uint4*)(Xs + r * GSTRIDE + c) = val;
    }
    __syncthreads();

    const int wm = warp & 3;
    const int wn = warp >> 2;
    const int qr = lane >> 2;
    const int kq = (lane & 3) * 2;

    float acc[2][8][4];
    #pragma unroll
    for (int m = 0; m < 2; ++m)
        #pragma unroll
        for (int nt = 0; nt < 8; ++nt)
            #pragma unroll
            for (int j = 0; j < 4; ++j) acc[m][nt][j] = 0.f;

    #pragma unroll
    for (int k0 = 0; k0 < D; k0 += 16) {
        unsigned a[2][4];
        #pragma unroll
        for (int m = 0; m < 2; ++m) {
            const __nv_bfloat16* base = Xs + (32 * wm + 16 * m + qr) * GSTRIDE + k0 + kq;
            a[m][0] = *(const unsigned*)(base);
            a[m][1] = *(const unsigned*)(base + 8 * GSTRIDE);
            a[m][2] = *(const unsigned*)(base + 8);
            a[m][3] = *(const unsigned*)(base + 8 * GSTRIDE + 8);
        }
        #pragma unroll
        for (int nt = 0; nt < 8; ++nt) {
            const __nv_bfloat16* bb = Ws + (64 * wn + nt * 8 + qr) * GSTRIDE + k0 + kq;
            unsigned b0 = *(const unsigned*)(bb);
            unsigned b1 = *(const unsigned*)(bb + 8);
            mma16816(acc[0][nt], a[0][0], a[0][1], a[0][2], a[0][3], b0, b1);
            mma16816(acc[1][nt], a[1][0], a[1][1], a[1][2], a[1][3], b0, b1);
        }
    }

    #pragma unroll
    for (int m = 0; m < 2; ++m) {
        int gr0 = row0 + 32 * wm + 16 * m + qr;
        int gr1 = gr0 + 8;
        #pragma unroll
        for (int nt = 0; nt < 8; ++nt) {
            int gc = 64 * wn + nt * 8 + kq;
            float b0f = bias[gc], b1f = bias[gc + 1];
            if (gr0 < N) {
                __nv_bfloat162 o = __floats2bfloat162_rn(acc[m][nt][0] + b0f, acc[m][nt][1] + b1f);
                *(__nv_bfloat162*)(C + (size_t)gr0 * cs + gc) = o;
            }
            if (gr1 < N) {
                __nv_bfloat162 o = __floats2bfloat162_rn(acc[m][nt][2] + b0f, acc[m][nt][3] + b1f);
                *(__nv_bfloat162*)(C + (size_t)gr1 * cs + gc) = o;
            }
        }
    }
}

// ---------------- CSR build (batched over both edge types) ----------------
struct CountB { const int* dst[2]; int* deg[2]; int E[2]; };

__global__ void count_b(CountB cb)
{
    const int t = blockIdx.y;
    const int* __restrict__ dst = cb.dst[t];
    int* __restrict__ deg = cb.deg[t];
    const int E = cb.E[t];
    for (int e = blockIdx.x * blockDim.x + threadIdx.x; e < E; e += gridDim.x * blockDim.x)
        atomicAdd(&deg[dst[e]], 1);
}

struct ScanB { const int* deg[2]; int* off[2]; int* cur[2]; int n[2]; };

__global__ __launch_bounds__(1024) void scan_b(ScanB sb)
{
    __shared__ int sh[1024];
    const int b = blockIdx.x;
    const int* __restrict__ deg = sb.deg[b];
    int* __restrict__ off = sb.off[b];
    int* __restrict__ cur = sb.cur[b];
    const int n = sb.n[b];
    int t = threadIdx.x;
    int c = (n + 1023) >> 10;
    int lo = t * c;
    int hi = lo + c; if (hi > n) hi = n;
    int s = 0;
    for (int i = lo; i < hi; ++i) s += deg[i];
    sh[t] = s;
    __syncthreads();
    for (int o = 1; o < 1024; o <<= 1) {
        int v = (t >= o) ? sh[t - o] : 0;
        __syncthreads();
        sh[t] += v;
        __syncthreads();
    }
    int base = sh[t] - s;
    for (int i = lo; i < hi; ++i) { off[i] = base; cur[i] = base; base += deg[i]; }
    if (t == 1023) off[n] = sh[1023];
}

struct FillB { const int* dst[2]; const int* src[2]; int* cur[2]; int* csrc[2]; int E[2]; };

__global__ void fill_b(FillB fb)
{
    const int t = blockIdx.y;
    const int* __restrict__ dst = fb.dst[t];
    const int* __restrict__ src = fb.src[t];
    int* __restrict__ cur = fb.cur[t];
    int* __restrict__ csrc = fb.csrc[t];
    const int E = fb.E[t];
    for (int e = blockIdx.x * blockDim.x + threadIdx.x; e < E; e += gridDim.x * blockDim.x) {
        int p = atomicAdd(&cur[dst[e]], 1);
        csrc[p] = src[e];
    }
}

// ------------- batched fused edge pass (both edge types), edge loop unrolled x4 ----------------
struct EdgeBatch {
    const __nv_bfloat16* qv[2];
    const __nv_bfloat16* k[2];
    const int* off[2];
    const int* csrc[2];
    __nv_bfloat16* agg[2];
    float* psum;                 // [2]
    int n[2];
};

__device__ __forceinline__ float edot(uint2 qr, float2 kl, float2 kh)
{
    float2 q0 = __bfloat1622float2(*(__nv_bfloat162*)&qr.x);
    float2 q1 = __bfloat1622float2(*(__nv_bfloat162*)&qr.y);
    return q0.x * kl.x + q0.y * kl.y + q1.x * kh.x + q1.y * kh.y;
}

__device__ __forceinline__ void eacc(float ex, uint2 vr,
                                     float& a0, float& a1, float& a2, float& a3)
{
    float2 v0 = __bfloat1622float2(*(__nv_bfloat162*)&vr.x);
    float2 v1 = __bfloat1622float2(*(__nv_bfloat162*)&vr.y);
    a0 = fmaf(ex, v0.x, a0);
    a1 = fmaf(ex, v0.y, a1);
    a2 = fmaf(ex, v1.x, a2);
    a3 = fmaf(ex, v1.y, a3);
}

__device__ __forceinline__ float lrexp(float p)
{
    float sc = p * 0.08838834764831845f;     // 1/sqrt(128)
    sc = sc > 0.f ? sc : 0.01f * sc;         // leaky_relu
    return __expf(sc);
}

__global__ __launch_bounds__(256) void fused_edge_batch(EdgeBatch eb)
{
    const int p    = blockIdx.y;
    const int lane = threadIdx.x & 31;
    const int warp = (blockIdx.x * 256 + threadIdx.x) >> 5;
    const int nw   = (gridDim.x * 256) >> 5;
    const __nv_bfloat16* __restrict__ qv = eb.qv[p];
    const __nv_bfloat16* __restrict__ kk = eb.k[p];
    const int* __restrict__ off  = eb.off[p];
    const int* __restrict__ csrc = eb.csrc[p];
    __nv_bfloat16* __restrict__ agg = eb.agg[p];
    const int n = eb.n[p];
    const int lo4 = lane * 4;

    float S = 0.f;
    for (int node = warp; node < n; node += nw) {
        uint2 kr = *(const uint2*)(kk + (size_t)node * D + lo4);
        float2 kl = __bfloat1622float2(*(__nv_bfloat162*)&kr.x);
        float2 kh = __bfloat1622float2(*(__nv_bfloat162*)&kr.y);
        float a0 = 0.f, a1 = 0.f, a2 = 0.f, a3 = 0.f;
        const int beg = off[node], end = off[node + 1];
        int idx = beg;
        for (; idx + 4 <= end; idx += 4) {
            const __nv_bfloat16* b0 = qv + (size_t)csrc[idx + 0] * QVS + lo4;
            const __nv_bfloat16* b1 = qv + (size_t)csrc[idx + 1] * QVS + lo4;
            const __nv_bfloat16* b2 = qv + (size_t)csrc[idx + 2] * QVS + lo4;
            const __nv_bfloat16* b3 = qv + (size_t)csrc[idx + 3] * QVS + lo4;
            uint2 q0 = *(const uint2*)(b0);
            uint2 q1 = *(const uint2*)(b1);
            uint2 q2 = *(const uint2*)(b2);
            uint2 q3 = *(const uint2*)(b3);
            uint2 v0 = *(const uint2*)(b0 + 128);
            uint2 v1 = *(const uint2*)(b1 + 128);
            uint2 v2 = *(const uint2*)(b2 + 128);
            uint2 v3 = *(const uint2*)(b3 + 128);
            float p0 = edot(q0, kl, kh);
            float p1 = edot(q1, kl, kh);
            float p2 = edot(q2, kl, kh);
            float p3 = edot(q3, kl, kh);
            #pragma unroll
            for (int o = 16; o; o >>= 1) {
                p0 += __shfl_xor_sync(0xffffffffu, p0, o);
                p1 += __shfl_xor_sync(0xffffffffu, p1, o);
                p2 += __shfl_xor_sync(0xffffffffu, p2, o);
                p3 += __shfl_xor_sync(0xffffffffu, p3, o);
            }
            float e0 = lrexp(p0);
            float e1 = lrexp(p1);
            float e2 = lrexp(p2);
            float e3 = lrexp(p3);
            eacc(e0, v0, a0, a1, a2, a3);
            eacc(e1, v1, a0, a1, a2, a3);
            eacc(e2, v2, a0, a1, a2, a3);
            eacc(e3, v3, a0, a1, a2, a3);
            S += (e0 + e1) + (e2 + e3);
        }
        for (; idx < end; ++idx) {
            const __nv_bfloat16* b0 = qv + (size_t)csrc[idx] * QVS + lo4;
            uint2 q0 = *(const uint2*)(b0);
            uint2 v0 = *(const uint2*)(b0 + 128);
            float p0 = edot(q0, kl, kh);
            #pragma unroll
            for (int o = 16; o; o >>= 1) p0 += __shfl_xor_sync(0xffffffffu, p0, o);
            float e0 = lrexp(p0);
            eacc(e0, v0, a0, a1, a2, a3);
            S += e0;
        }
        __nv_bfloat162 lo = __floats2bfloat162_rn(a0, a1);
        __nv_bfloat162 hi = __floats2bfloat162_rn(a2, a3);
        uint2 ob;
        ob.x = *(unsigned int*)&lo;
        ob.y = *(unsigned int*)&hi;
        *(uint2*)(agg + (size_t)node * D + lo4) = ob;
    }
    // one atomic per warp for the global softmax denominator
    if (lane == 0 && S != 0.f) atomicAdd(&eb.psum[p], S);
}

// ---------------- out = x + agg / S for both node types; optional bf16 emit ----------------
struct AxpyBatch {
    const float* xin[2];
    const __nv_bfloat16* agg[2];
    const float* gsum[2];
    float* out[2];
    __nv_bfloat16* outb[2];
    int n4[2];
};

__global__ void axpy_batch(AxpyBatch ab)
{
    const int t = blockIdx.y;
    int i = blockIdx.x * blockDim.x + threadIdx.x;
    if (i >= ab.n4[t]) return;
    float inv = 1.0f / *ab.gsum[t];
    float4 x = ((const float4*)ab.xin[t])[i];
    uint2 ag = ((const uint2*)ab.agg[t])[i];
    float2 al = __bfloat1622float2(*(__nv_bfloat162*)&ag.x);
    float2 ah = __bfloat1622float2(*(__nv_bfloat162*)&ag.y);
    float4 o;
    o.x = fmaf(inv, al.x, x.x);
    o.y = fmaf(inv, al.y, x.y);
    o.z = fmaf(inv, ah.x, x.z);
    o.w = fmaf(inv, ah.y, x.w);
    ((float4*)ab.out[t])[i] = o;
    if (ab.outb[t]) {
        __nv_bfloat162 lo = __floats2bfloat162_rn(o.x, o.y);
        __nv_bfloat162 hi = __floats2bfloat162_rn(o.z, o.w);
        uint2 ob;
        ob.x = *(unsigned int*)&lo;
        ob.y = *(unsigned int*)&hi;
        ((uint2*)ab.outb[t])[i] = ob;
    }
}

// ---------------- host-side orchestration ----------------
#define GEMM_SMEM (2 * 128 * GSTRIDE * (int)sizeof(__nv_bfloat16))

extern "C" void kernel_launch(void* const* d_in, const int* in_sizes, int n_in,
                              void* d_out, int out_size)
{
    const float* x_user = (const float*)d_in[0];
    const float* x_item = (const float*)d_in[1];
    const int*   ei_ui  = (const int*)d_in[2];
    const int*   ei_iu  = (const int*)d_in[3];
    const float* q_w_user = (const float*)d_in[4];
    const float* q_b_user = (const float*)d_in[5];
    const float* k_w_user = (const float*)d_in[6];
    const float* k_b_user = (const float*)d_in[7];
    const float* v_w_user = (const float*)d_in[8];
    const float* v_b_user = (const float*)d_in[9];
    const float* q_w_item = (const float*)d_in[10];
    const float* q_b_item = (const float*)d_in[11];
    const float* k_w_item = (const float*)d_in[12];
    const float* k_b_item = (const float*)d_in[13];
    const float* v_w_item = (const float*)d_in[14];
    const float* v_b_item = (const float*)d_in[15];
    const float* W_ui = (const float*)d_in[16];
    const float* W_iu = (const float*)d_in[17];

    const int NU = in_sizes[0] / D;
    const int NI = in_sizes[1] / D;
    const int E_ui = in_sizes[2] / 2;
    const int E_iu = in_sizes[3] / 2;

    cudaFuncSetAttribute(gemm_batch, cudaFuncAttributeMaxDynamicSharedMemorySize, GEMM_SMEM);

    float *yu, *yi, *cb, *psum;
    __nv_bfloat16 *agg0, *agg1, *xbu, *xbi, *qv0, *qv1, *kb0, *kb1, *Mtb, *Kb, *Vb;
    int *deg0, *deg1, *cur0, *cur1, *off_ui, *off_iu, *src_ui_c, *src_iu_c;
    cudaGetSymbolAddress((void**)&yu, g_yu);
    cudaGetSymbolAddress((void**)&yi, g_yi);
    cudaGetSymbolAddress((void**)&agg0, g_agg);
    agg1 = agg0 + (size_t)MAXN * D;
    cudaGetSymbolAddress((void**)&xbu, g_xbu);
    cudaGetSymbolAddress((void**)&xbi, g_xbi);
    cudaGetSymbolAddress((void**)&qv0, g_qv);
    qv1 = qv0 + (size_t)MAXN * QVS;
    cudaGetSymbolAddress((void**)&kb0, g_k);
    kb1 = kb0 + (size_t)MAXN * D;
    cudaGetSymbolAddress((void**)&Mtb, g_Mtb);       // [4][D*D]
    cudaGetSymbolAddress((void**)&Kb, g_Kb);
    cudaGetSymbolAddress((void**)&Vb, g_Vb);
    cudaGetSymbolAddress((void**)&cb, g_cb);         // [4][D]
    cudaGetSymbolAddress((void**)&psum, g_sum);      // [4]
    cudaGetSymbolAddress((void**)&deg0, g_deg);
    deg1 = deg0 + MAXN;
    cudaGetSymbolAddress((void**)&cur0, g_cur);
    cur1 = cur0 + MAXN;
    cudaGetSymbolAddress((void**)&off_ui, g_off_ui);
    cudaGetSymbolAddress((void**)&off_iu, g_off_iu);
    cudaGetSymbolAddress((void**)&src_ui_c, g_src_ui);
    cudaGetSymbolAddress((void**)&src_iu_c, g_src_iu);

    const int* src_ui = ei_ui;
    const int* dst_ui = ei_ui + E_ui;
    const int* src_iu = ei_iu;
    const int* dst_iu = ei_iu + E_iu;

    // --- CSR by dst for both edge types (3 batched launches; built once, reused by both layers) ---
    cudaMemsetAsync(deg0, 0, 2 * (size_t)MAXN * sizeof(int));
    CountB cbt;
    cbt.dst[0] = dst_ui; cbt.deg[0] = deg0; cbt.E[0] = E_ui;
    cbt.dst[1] = dst_iu; cbt.deg[1] = deg1; cbt.E[1] = E_iu;
    count_b<<<dim3(512, 2), 256>>>(cbt);
    ScanB sbt;
    sbt.deg[0] = deg0; sbt.off[0] = off_ui; sbt.cur[0] = cur0; sbt.n[0] = NI;
    sbt.deg[1] = deg1; sbt.off[1] = off_iu; sbt.cur[1] = cur1; sbt.n[1] = NU;
    scan_b<<<2, 1024>>>(sbt);
    FillB fbt;
    fbt.dst[0] = dst_ui; fbt.src[0] = src_ui; fbt.cur[0] = cur0; fbt.csrc[0] = src_ui_c; fbt.E[0] = E_ui;
    fbt.dst[1] = dst_iu; fbt.src[1] = src_iu; fbt.cur[1] = cur1; fbt.csrc[1] = src_iu_c; fbt.E[1] = E_iu;
    fill_b<<<dim3(512, 2), 256>>>(fbt);

    // --- bf16 copies of layer-0 inputs ---
    const int maxN = (NU > NI) ? NU : NI;
    ConvB cv;
    cv.x[0] = x_user; cv.y[0] = xbu; cv.n4[0] = NU * D / 4;
    cv.x[1] = x_item; cv.y[1] = xbi; cv.n4[1] = NI * D / 4;
    conv_b16<<<dim3((maxN * D / 4 + 255) / 256, 2), 256>>>(cv);

    // --- all 4 weight preps up front (p = layer*2 + edgetype) ---
    {
        PrepBatch pb;
        for (int l = 0; l < 2; ++l) {
            const size_t wo = (size_t)l * D * D;
            const size_t bo = (size_t)l * D;
            pb.qw[2*l+0] = q_w_user + wo; pb.qb[2*l+0] = q_b_user + bo; pb.W[2*l+0] = W_ui + wo;
            pb.kw[2*l+0] = k_w_item + wo; pb.vw[2*l+0] = v_w_user + wo;
            pb.qw[2*l+1] = q_w_item + wo; pb.qb[2*l+1] = q_b_item + bo; pb.W[2*l+1] = W_iu + wo;
            pb.kw[2*l+1] = k_w_user + wo; pb.vw[2*l+1] = v_w_item + wo;
        }
        pb.Mtb = Mtb; pb.Kb = Kb; pb.Vb = Vb; pb.cb = cb; pb.psum = psum;
        prep_batch<<<dim3(193, 4), 256>>>(pb);
    }

    float* out_f = (float*)d_out;

    for (int l = 0; l < 2; ++l) {
        const float* in_u = (l == 0) ? x_user : yu;
        const float* in_i = (l == 0) ? x_item : yi;
        float* out_u = (l == 0) ? yu : out_f;
        float* out_i = (l == 0) ? yi : (out_f + (size_t)NU * D);

        const size_t bo = (size_t)l * D;
        const int p0 = 2 * l, p1 = 2 * l + 1;

        GemmBatch gb;
        // pass 0: user->item (q/v from user, k from item)
        gb.X[0] = xbu; gb.W[0] = Mtb + p0 * D * D; gb.bias[0] = cb + p0 * D;    gb.C[0] = qv0;       gb.N[0] = NU; gb.cs[0] = QVS;
        gb.X[1] = xbi; gb.W[1] = Kb + p0 * D * D;  gb.bias[1] = k_b_item + bo; gb.C[1] = kb0;       gb.N[1] = NI; gb.cs[1] = D;
        gb.X[2] = xbu; gb.W[2] = Vb + p0 * D * D;  gb.bias[2] = v_b_user + bo; gb.C[2] = qv0 + 128; gb.N[2] = NU; gb.cs[2] = QVS;
        // pass 1: item->user (q/v from item, k from user)
        gb.X[3] = xbi; gb.W[3] = Mtb + p1 * D * D; gb.bias[3] = cb + p1 * D;    gb.C[3] = qv1;       gb.N[3] = NI; gb.cs[3] = QVS;
        gb.X[4] = xbu; gb.W[4] = Kb + p1 * D * D;  gb.bias[4] = k_b_user + bo; gb.C[4] = kb1;       gb.N[4] = NU; gb.cs[4] = D;
        gb.X[5] = xbi; gb.W[5] = Vb + p1 * D * D;  gb.bias[5] = v_b_item + bo; gb.C[5] = qv1 + 128; gb.N[5] = NI; gb.cs[5] = QVS;
        gemm_batch<<<dim3((maxN + 127) / 128, 6), 256, GEMM_SMEM>>>(gb);

        EdgeBatch eb;
        eb.qv[0] = qv0; eb.k[0] = kb0;
        eb.off[0] = off_ui; eb.csrc[0] = src_ui_c; eb.agg[0] = agg0; eb.n[0] = NI;
        eb.qv[1] = qv1; eb.k[1] = kb1;
        eb.off[1] = off_iu; eb.csrc[1] = src_iu_c; eb.agg[1] = agg1; eb.n[1] = NU;
        eb.psum = psum + 2 * l;
        fused_edge_batch<<<dim3(1024, 2), 256>>>(eb);

        AxpyBatch ab;
        ab.xin[0] = in_u; ab.agg[0] = agg1; ab.gsum[0] = psum + p1; ab.out[0] = out_u;
        ab.outb[0] = (l == 0) ? xbu : (__nv_bfloat16*)nullptr; ab.n4[0] = NU * D / 4;
        ab.xin[1] = in_i; ab.agg[1] = agg0; ab.gsum[1] = psum + p0; ab.out[1] = out_i;
        ab.outb[1] = (l == 0) ? xbi : (__nv_bfloat16*)nullptr; ab.n4[1] = NI * D / 4;
        axpy_batch<<<dim3((maxN * D / 4 + 255) / 256, 2), 256>>>(ab);
    }
}

// round 7
// speedup vs baseline: 1.5151x; 1.5151x over previous
#include <cuda_runtime.h>
#include <cuda_bf16.h>
#include <math.h>

#define D 128
#define QVS 256                   // qv row stride (q at 0..127, v at 128..255)
#define MAXN 50000
#define MAXE 600000

// ---------------- scratch (static device globals; no allocation) ----------------
__device__ float          g_yu[MAXN * D];
__device__ float          g_yi[MAXN * D];
__device__ __nv_bfloat16  g_agg[2][MAXN * D];        // 0: items (ui pass), 1: users (iu pass)
__device__ __nv_bfloat16  g_xbu[MAXN * D];
__device__ __nv_bfloat16  g_xbi[MAXN * D];
__device__ __nv_bfloat16  g_qv[2][MAXN * QVS];       // interleaved q|v per pass
__device__ __nv_bfloat16  g_k[2][MAXN * D];
__device__ __nv_bfloat16  g_Mtb[4][D * D];           // 4 = 2 layers x 2 passes
__device__ __nv_bfloat16  g_Kb[4][D * D];
__device__ __nv_bfloat16  g_Vb[4][D * D];
__device__ float          g_cb[4][D];
__device__ float          g_sum[4];
__device__ int            g_deg[2][MAXN];
__device__ int            g_cur[2][MAXN];
__device__ int            g_off_ui[MAXN + 1];
__device__ int            g_off_iu[MAXN + 1];
__device__ int            g_src_ui[MAXE];
__device__ int            g_src_iu[MAXE];

// ---------------- all-layer weight prep (4 passes: layer*2 + edgetype) ----------------
struct PrepBatch {
    const float* qw[4]; const float* qb[4]; const float* W[4];
    const float* kw[4]; const float* vw[4];
    __nv_bfloat16* Mtb; __nv_bfloat16* Kb; __nv_bfloat16* Vb;
    float* cb; float* psum;
};

__global__ void prep_batch(PrepBatch pb)
{
    const int p  = blockIdx.y;
    const int bx = blockIdx.x;
    if (bx == 0 && threadIdx.x == 0) pb.psum[p] = 0.f;
    if (bx < 65) {
        int id = bx * 256 + threadIdx.x;
        if (id < D * D) {
            int j = id / D, d = id % D;
            const float* qw = pb.qw[p];
            const float* W  = pb.W[p];
            float s = 0.f;
            #pragma unroll 8
            for (int e = 0; e < D; ++e) s = fmaf(qw[e * D + d], W[e * D + j], s);
            pb.Mtb[p * D * D + j * D + d] = __float2bfloat16(s);
        } else if (id < D * D + D) {
            int j = id - D * D;
            const float* qb = pb.qb[p];
            const float* W  = pb.W[p];
            float s = 0.f;
            #pragma unroll 8
            for (int e = 0; e < D; ++e) s = fmaf(qb[e], W[e * D + j], s);
            pb.cb[p * D + j] = s;
        }
    } else if (bx < 129) {
        int id = (bx - 65) * 256 + threadIdx.x;
        pb.Kb[p * D * D + id] = __float2bfloat16(pb.kw[p][id]);
    } else {
        int id = (bx - 129) * 256 + threadIdx.x;
        pb.Vb[p * D * D + id] = __float2bfloat16(pb.vw[p][id]);
    }
}

// ---------------- batched fp32 -> bf16 convert ----------------
struct ConvB { const float* x[2]; __nv_bfloat16* y[2]; int n4[2]; };

__global__ void conv_b16(ConvB cv)
{
    const int t = blockIdx.y;
    int i = blockIdx.x * blockDim.x + threadIdx.x;
    if (i >= cv.n4[t]) return;
    float4 v = ((const float4*)cv.x[t])[i];
    __nv_bfloat162 lo = __floats2bfloat162_rn(v.x, v.y);
    __nv_bfloat162 hi = __floats2bfloat162_rn(v.z, v.w);
    uint2 o;
    o.x = *(unsigned int*)&lo;
    o.y = *(unsigned int*)&hi;
    ((uint2*)cv.y[t])[i] = o;
}

// ---------------- bf16 tensor-core batched GEMM: C[N,128] = bf16(X @ Wm^T + bias) ----------------
__device__ __forceinline__ void mma16816(float c[4],
                                         unsigned a0, unsigned a1, unsigned a2, unsigned a3,
                                         unsigned b0, unsigned b1)
{
    asm volatile("mma.sync.aligned.m16n8k16.row.col.f32.bf16.bf16.f32 "
                 "{%0,%1,%2,%3}, {%4,%5,%6,%7}, {%8,%9}, {%0,%1,%2,%3};"
                 : "+f"(c[0]), "+f"(c[1]), "+f"(c[2]), "+f"(c[3])
                 : "r"(a0), "r"(a1), "r"(a2), "r"(a3), "r"(b0), "r"(b1));
}

#define GSTRIDE 136   // smem row stride in bf16 elems; 68 words, 68 mod 32 = 4 -> conflict-free

struct GemmBatch {
    const __nv_bfloat16* X[6];
    const __nv_bfloat16* W[6];
    const float*         bias[6];
    __nv_bfloat16*       C[6];
    int                  N[6];
    int                  cs[6];     // output row stride
};

__global__ __launch_bounds__(256, 2) void gemm_batch(GemmBatch gb)
{
    extern __shared__ __nv_bfloat16 sh[];
    __nv_bfloat16* Xs = sh;                   // [128][GSTRIDE]
    __nv_bfloat16* Ws = sh + 128 * GSTRIDE;   // [128][GSTRIDE]
    const int g = blockIdx.y;
    const int N = gb.N[g];
    const int row0 = blockIdx.x * 128;
    if (row0 >= N) return;
    const __nv_bfloat16* __restrict__ X  = gb.X[g];
    const __nv_bfloat16* __restrict__ Wm = gb.W[g];
    const float* __restrict__ bias       = gb.bias[g];
    __nv_bfloat16* __restrict__ C        = gb.C[g];
    const int cs = gb.cs[g];

    const int tid  = threadIdx.x;
    const int warp = tid >> 5, lane = tid & 31;

    #pragma unroll
    for (int i = 0; i < 8; ++i) {
        int seg = tid + i * 256;
        int r = seg >> 4, c = (seg & 15) << 3;
        *(uint4*)(Ws + r * GSTRIDE + c) = *(const uint4*)(Wm + r * D + c);
    }
    #pragma unroll
    for (int i = 0; i < 8; ++i) {
        int seg = tid + i * 256;
        int r = seg >> 4, c = (seg & 15) << 3;
        int gr = row0 + r;
        uint4 val = make_uint4(0u, 0u, 0u, 0u);
        if (gr < N) val = *(const uint4*)(X + (size_t)gr * D + c);
        *(uint4*)(Xs + r * GSTRIDE + c) = val;
    }
    __syncthreads();

    const int wm = warp & 3;
    const int wn = warp >> 2;
    const int qr = lane >> 2;
    const int kq = (lane & 3) * 2;

    float acc[2][8][4];
    #pragma unroll
    for (int m = 0; m < 2; ++m)
        #pragma unroll
        for (int nt = 0; nt < 8; ++nt)
            #pragma unroll
            for (int j = 0; j < 4; ++j) acc[m][nt][j] = 0.f;

    #pragma unroll
    for (int k0 = 0; k0 < D; k0 += 16) {
        unsigned a[2][4];
        #pragma unroll
        for (int m = 0; m < 2; ++m) {
            const __nv_bfloat16* base = Xs + (32 * wm + 16 * m + qr) * GSTRIDE + k0 + kq;
            a[m][0] = *(const unsigned*)(base);
            a[m][1] = *(const unsigned*)(base + 8 * GSTRIDE);
            a[m][2] = *(const unsigned*)(base + 8);
            a[m][3] = *(const unsigned*)(base + 8 * GSTRIDE + 8);
        }
        #pragma unroll
        for (int nt = 0; nt < 8; ++nt) {
            const __nv_bfloat16* bb = Ws + (64 * wn + nt * 8 + qr) * GSTRIDE + k0 + kq;
            unsigned b0 = *(const unsigned*)(bb);
            unsigned b1 = *(const unsigned*)(bb + 8);
            mma16816(acc[0][nt], a[0][0], a[0][1], a[0][2], a[0][3], b0, b1);
            mma16816(acc[1][nt], a[1][0], a[1][1], a[1][2], a[1][3], b0, b1);
        }
    }

    #pragma unroll
    for (int m = 0; m < 2; ++m) {
        int gr0 = row0 + 32 * wm + 16 * m + qr;
        int gr1 = gr0 + 8;
        #pragma unroll
        for (int nt = 0; nt < 8; ++nt) {
            int gc = 64 * wn + nt * 8 + kq;
            float b0f = bias[gc], b1f = bias[gc + 1];
            if (gr0 < N) {
                __nv_bfloat162 o = __floats2bfloat162_rn(acc[m][nt][0] + b0f, acc[m][nt][1] + b1f);
                *(__nv_bfloat162*)(C + (size_t)gr0 * cs + gc) = o;
            }
            if (gr1 < N) {
                __nv_bfloat162 o = __floats2bfloat162_rn(acc[m][nt][2] + b0f, acc[m][nt][3] + b1f);
                *(__nv_bfloat162*)(C + (size_t)gr1 * cs + gc) = o;
            }
        }
    }
}

// ---------------- CSR build (batched over both edge types) ----------------
struct CountB { const int* dst[2]; int* deg[2]; int E[2]; };

__global__ void count_b(CountB cb)
{
    const int t = blockIdx.y;
    const int* __restrict__ dst = cb.dst[t];
    int* __restrict__ deg = cb.deg[t];
    const int E = cb.E[t];
    for (int e = blockIdx.x * blockDim.x + threadIdx.x; e < E; e += gridDim.x * blockDim.x)
        atomicAdd(&deg[dst[e]], 1);
}

struct ScanB { const int* deg[2]; int* off[2]; int* cur[2]; int n[2]; };

__global__ __launch_bounds__(1024) void scan_b(ScanB sb)
{
    __shared__ int sh[1024];
    const int b = blockIdx.x;
    const int* __restrict__ deg = sb.deg[b];
    int* __restrict__ off = sb.off[b];
    int* __restrict__ cur = sb.cur[b];
    const int n = sb.n[b];
    int t = threadIdx.x;
    int c = (n + 1023) >> 10;
    int lo = t * c;
    int hi = lo + c; if (hi > n) hi = n;
    int s = 0;
    for (int i = lo; i < hi; ++i) s += deg[i];
    sh[t] = s;
    __syncthreads();
    for (int o = 1; o < 1024; o <<= 1) {
        int v = (t >= o) ? sh[t - o] : 0;
        __syncthreads();
        sh[t] += v;
        __syncthreads();
    }
    int base = sh[t] - s;
    for (int i = lo; i < hi; ++i) { off[i] = base; cur[i] = base; base += deg[i]; }
    if (t == 1023) off[n] = sh[1023];
}

struct FillB { const int* dst[2]; const int* src[2]; int* cur[2]; int* csrc[2]; int E[2]; };

__global__ void fill_b(FillB fb)
{
    const int t = blockIdx.y;
    const int* __restrict__ dst = fb.dst[t];
    const int* __restrict__ src = fb.src[t];
    int* __restrict__ cur = fb.cur[t];
    int* __restrict__ csrc = fb.csrc[t];
    const int E = fb.E[t];
    for (int e = blockIdx.x * blockDim.x + threadIdx.x; e < E; e += gridDim.x * blockDim.x) {
        int p = atomicAdd(&cur[dst[e]], 1);
        csrc[p] = src[e];
    }
}

// ------------- batched fused edge pass (both edge types), edge loop unrolled x4 ----------------
struct EdgeBatch {
    const __nv_bfloat16* qv[2];
    const __nv_bfloat16* k[2];
    const int* off[2];
    const int* csrc[2];
    __nv_bfloat16* agg[2];
    float* psum;                 // [2]
    int n[2];
};

__device__ __forceinline__ float edot(uint2 qr, float2 kl, float2 kh)
{
    float2 q0 = __bfloat1622float2(*(__nv_bfloat162*)&qr.x);
    float2 q1 = __bfloat1622float2(*(__nv_bfloat162*)&qr.y);
    return q0.x * kl.x + q0.y * kl.y + q1.x * kh.x + q1.y * kh.y;
}

__device__ __forceinline__ void eacc(float ex, uint2 vr,
                                     float& a0, float& a1, float& a2, float& a3)
{
    float2 v0 = __bfloat1622float2(*(__nv_bfloat162*)&vr.x);
    float2 v1 = __bfloat1622float2(*(__nv_bfloat162*)&vr.y);
    a0 = fmaf(ex, v0.x, a0);
    a1 = fmaf(ex, v0.y, a1);
    a2 = fmaf(ex, v1.x, a2);
    a3 = fmaf(ex, v1.y, a3);
}

__device__ __forceinline__ float lrexp(float p)
{
    float sc = p * 0.08838834764831845f;     // 1/sqrt(128)
    sc = sc > 0.f ? sc : 0.01f * sc;         // leaky_relu
    return __expf(sc);
}

__global__ __launch_bounds__(256) void fused_edge_batch(EdgeBatch eb)
{
    const int p    = blockIdx.y;
    const int lane = threadIdx.x & 31;
    const int warp = (blockIdx.x * 256 + threadIdx.x) >> 5;
    const int nw   = (gridDim.x * 256) >> 5;
    const __nv_bfloat16* __restrict__ qv = eb.qv[p];
    const __nv_bfloat16* __restrict__ kk = eb.k[p];
    const int* __restrict__ off  = eb.off[p];
    const int* __restrict__ csrc = eb.csrc[p];
    __nv_bfloat16* __restrict__ agg = eb.agg[p];
    const int n = eb.n[p];
    const int lo4 = lane * 4;

    float S = 0.f;
    for (int node = warp; node < n; node += nw) {
        uint2 kr = *(const uint2*)(kk + (size_t)node * D + lo4);
        float2 kl = __bfloat1622float2(*(__nv_bfloat162*)&kr.x);
        float2 kh = __bfloat1622float2(*(__nv_bfloat162*)&kr.y);
        float a0 = 0.f, a1 = 0.f, a2 = 0.f, a3 = 0.f;
        const int beg = off[node], end = off[node + 1];
        int idx = beg;
        for (; idx + 4 <= end; idx += 4) {
            const __nv_bfloat16* b0 = qv + (size_t)csrc[idx + 0] * QVS + lo4;
            const __nv_bfloat16* b1 = qv + (size_t)csrc[idx + 1] * QVS + lo4;
            const __nv_bfloat16* b2 = qv + (size_t)csrc[idx + 2] * QVS + lo4;
            const __nv_bfloat16* b3 = qv + (size_t)csrc[idx + 3] * QVS + lo4;
            uint2 q0 = *(const uint2*)(b0);
            uint2 q1 = *(const uint2*)(b1);
            uint2 q2 = *(const uint2*)(b2);
            uint2 q3 = *(const uint2*)(b3);
            uint2 v0 = *(const uint2*)(b0 + 128);
            uint2 v1 = *(const uint2*)(b1 + 128);
            uint2 v2 = *(const uint2*)(b2 + 128);
            uint2 v3 = *(const uint2*)(b3 + 128);
            float p0 = edot(q0, kl, kh);
            float p1 = edot(q1, kl, kh);
            float p2 = edot(q2, kl, kh);
            float p3 = edot(q3, kl, kh);
            #pragma unroll
            for (int o = 16; o; o >>= 1) {
                p0 += __shfl_xor_sync(0xffffffffu, p0, o);
                p1 += __shfl_xor_sync(0xffffffffu, p1, o);
                p2 += __shfl_xor_sync(0xffffffffu, p2, o);
                p3 += __shfl_xor_sync(0xffffffffu, p3, o);
            }
            float e0 = lrexp(p0);
            float e1 = lrexp(p1);
            float e2 = lrexp(p2);
            float e3 = lrexp(p3);
            eacc(e0, v0, a0, a1, a2, a3);
            eacc(e1, v1, a0, a1, a2, a3);
            eacc(e2, v2, a0, a1, a2, a3);
            eacc(e3, v3, a0, a1, a2, a3);
            S += (e0 + e1) + (e2 + e3);
        }
        for (; idx < end; ++idx) {
            const __nv_bfloat16* b0 = qv + (size_t)csrc[idx] * QVS + lo4;
            uint2 q0 = *(const uint2*)(b0);
            uint2 v0 = *(const uint2*)(b0 + 128);
            float p0 = edot(q0, kl, kh);
            #pragma unroll
            for (int o = 16; o; o >>= 1) p0 += __shfl_xor_sync(0xffffffffu, p0, o);
            float e0 = lrexp(p0);
            eacc(e0, v0, a0, a1, a2, a3);
            S += e0;
        }
        __nv_bfloat162 lo = __floats2bfloat162_rn(a0, a1);
        __nv_bfloat162 hi = __floats2bfloat162_rn(a2, a3);
        uint2 ob;
        ob.x = *(unsigned int*)&lo;
        ob.y = *(unsigned int*)&hi;
        *(uint2*)(agg + (size_t)node * D + lo4) = ob;
    }
    // one atomic per warp for the global softmax denominator
    if (lane == 0 && S != 0.f) atomicAdd(&eb.psum[p], S);
}

// ---------------- out = x + agg / S for both node types; optional bf16 emit ----------------
struct AxpyBatch {
    const float* xin[2];
    const __nv_bfloat16* agg[2];
    const float* gsum[2];
    float* out[2];
    __nv_bfloat16* outb[2];
    int n4[2];
};

__global__ void axpy_batch(AxpyBatch ab)
{
    const int t = blockIdx.y;
    int i = blockIdx.x * blockDim.x + threadIdx.x;
    if (i >= ab.n4[t]) return;
    float inv = 1.0f / *ab.gsum[t];
    float4 x = ((const float4*)ab.xin[t])[i];
    uint2 ag = ((const uint2*)ab.agg[t])[i];
    float2 al = __bfloat1622float2(*(__nv_bfloat162*)&ag.x);
    float2 ah = __bfloat1622float2(*(__nv_bfloat162*)&ag.y);
    float4 o;
    o.x = fmaf(inv, al.x, x.x);
    o.y = fmaf(inv, al.y, x.y);
    o.z = fmaf(inv, ah.x, x.z);
    o.w = fmaf(inv, ah.y, x.w);
    ((float4*)ab.out[t])[i] = o;
    if (ab.outb[t]) {
        __nv_bfloat162 lo = __floats2bfloat162_rn(o.x, o.y);
        __nv_bfloat162 hi = __floats2bfloat162_rn(o.z, o.w);
        uint2 ob;
        ob.x = *(unsigned int*)&lo;
        ob.y = *(unsigned int*)&hi;
        ((uint2*)ab.outb[t])[i] = ob;
    }
}

// ---------------- host-side orchestration ----------------
#define GEMM_SMEM (2 * 128 * GSTRIDE * (int)sizeof(__nv_bfloat16))

extern "C" void kernel_launch(void* const* d_in, const int* in_sizes, int n_in,
                              void* d_out, int out_size)
{
    const float* x_user = (const float*)d_in[0];
    const float* x_item = (const float*)d_in[1];
    const int*   ei_ui  = (const int*)d_in[2];
    const int*   ei_iu  = (const int*)d_in[3];
    const float* q_w_user = (const float*)d_in[4];
    const float* q_b_user = (const float*)d_in[5];
    const float* k_w_user = (const float*)d_in[6];
    const float* k_b_user = (const float*)d_in[7];
    const float* v_w_user = (const float*)d_in[8];
    const float* v_b_user = (const float*)d_in[9];
    const float* q_w_item = (const float*)d_in[10];
    const float* q_b_item = (const float*)d_in[11];
    const float* k_w_item = (const float*)d_in[12];
    const float* k_b_item = (const float*)d_in[13];
    const float* v_w_item = (const float*)d_in[14];
    const float* v_b_item = (const float*)d_in[15];
    const float* W_ui = (const float*)d_in[16];
    const float* W_iu = (const float*)d_in[17];

    const int NU = in_sizes[0] / D;
    const int NI = in_sizes[1] / D;
    const int E_ui = in_sizes[2] / 2;
    const int E_iu = in_sizes[3] / 2;

    cudaFuncSetAttribute(gemm_batch, cudaFuncAttributeMaxDynamicSharedMemorySize, GEMM_SMEM);

    float *yu, *yi, *cb, *psum;
    __nv_bfloat16 *agg0, *agg1, *xbu, *xbi, *qv0, *qv1, *kb0, *kb1, *Mtb, *Kb, *Vb;
    int *deg0, *deg1, *cur0, *cur1, *off_ui, *off_iu, *src_ui_c, *src_iu_c;
    cudaGetSymbolAddress((void**)&yu, g_yu);
    cudaGetSymbolAddress((void**)&yi, g_yi);
    cudaGetSymbolAddress((void**)&agg0, g_agg);
    agg1 = agg0 + (size_t)MAXN * D;
    cudaGetSymbolAddress((void**)&xbu, g_xbu);
    cudaGetSymbolAddress((void**)&xbi, g_xbi);
    cudaGetSymbolAddress((void**)&qv0, g_qv);
    qv1 = qv0 + (size_t)MAXN * QVS;
    cudaGetSymbolAddress((void**)&kb0, g_k);
    kb1 = kb0 + (size_t)MAXN * D;
    cudaGetSymbolAddress((void**)&Mtb, g_Mtb);       // [4][D*D]
    cudaGetSymbolAddress((void**)&Kb, g_Kb);
    cudaGetSymbolAddress((void**)&Vb, g_Vb);
    cudaGetSymbolAddress((void**)&cb, g_cb);         // [4][D]
    cudaGetSymbolAddress((void**)&psum, g_sum);      // [4]
    cudaGetSymbolAddress((void**)&deg0, g_deg);
    deg1 = deg0 + MAXN;
    cudaGetSymbolAddress((void**)&cur0, g_cur);
    cur1 = cur0 + MAXN;
    cudaGetSymbolAddress((void**)&off_ui, g_off_ui);
    cudaGetSymbolAddress((void**)&off_iu, g_off_iu);
    cudaGetSymbolAddress((void**)&src_ui_c, g_src_ui);
    cudaGetSymbolAddress((void**)&src_iu_c, g_src_iu);

    const int* src_ui = ei_ui;
    const int* dst_ui = ei_ui + E_ui;
    const int* src_iu = ei_iu;
    const int* dst_iu = ei_iu + E_iu;

    // --- CSR by dst for both edge types (3 batched launches; built once, reused by both layers) ---
    cudaMemsetAsync(deg0, 0, 2 * (size_t)MAXN * sizeof(int));
    CountB cbt;
    cbt.dst[0] = dst_ui; cbt.deg[0] = deg0; cbt.E[0] = E_ui;
    cbt.dst[1] = dst_iu; cbt.deg[1] = deg1; cbt.E[1] = E_iu;
    count_b<<<dim3(512, 2), 256>>>(cbt);
    ScanB sbt;
    sbt.deg[0] = deg0; sbt.off[0] = off_ui; sbt.cur[0] = cur0; sbt.n[0] = NI;
    sbt.deg[1] = deg1; sbt.off[1] = off_iu; sbt.cur[1] = cur1; sbt.n[1] = NU;
    scan_b<<<2, 1024>>>(sbt);
    FillB fbt;
    fbt.dst[0] = dst_ui; fbt.src[0] = src_ui; fbt.cur[0] = cur0; fbt.csrc[0] = src_ui_c; fbt.E[0] = E_ui;
    fbt.dst[1] = dst_iu; fbt.src[1] = src_iu; fbt.cur[1] = cur1; fbt.csrc[1] = src_iu_c; fbt.E[1] = E_iu;
    fill_b<<<dim3(512, 2), 256>>>(fbt);

    // --- bf16 copies of layer-0 inputs ---
    const int maxN = (NU > NI) ? NU : NI;
    ConvB cv;
    cv.x[0] = x_user; cv.y[0] = xbu; cv.n4[0] = NU * D / 4;
    cv.x[1] = x_item; cv.y[1] = xbi; cv.n4[1] = NI * D / 4;
    conv_b16<<<dim3((maxN * D / 4 + 255) / 256, 2), 256>>>(cv);

    // --- all 4 weight preps up front (p = layer*2 + edgetype) ---
    {
        PrepBatch pb;
        for (int l = 0; l < 2; ++l) {
            const size_t wo = (size_t)l * D * D;
            const size_t bo = (size_t)l * D;
            pb.qw[2*l+0] = q_w_user + wo; pb.qb[2*l+0] = q_b_user + bo; pb.W[2*l+0] = W_ui + wo;
            pb.kw[2*l+0] = k_w_item + wo; pb.vw[2*l+0] = v_w_user + wo;
            pb.qw[2*l+1] = q_w_item + wo; pb.qb[2*l+1] = q_b_item + bo; pb.W[2*l+1] = W_iu + wo;
            pb.kw[2*l+1] = k_w_user + wo; pb.vw[2*l+1] = v_w_item + wo;
        }
        pb.Mtb = Mtb; pb.Kb = Kb; pb.Vb = Vb; pb.cb = cb; pb.psum = psum;
        prep_batch<<<dim3(193, 4), 256>>>(pb);
    }

    float* out_f = (float*)d_out;

    for (int l = 0; l < 2; ++l) {
        const float* in_u = (l == 0) ? x_user : yu;
        const float* in_i = (l == 0) ? x_item : yi;
        float* out_u = (l == 0) ? yu : out_f;
        float* out_i = (l == 0) ? yi : (out_f + (size_t)NU * D);

        const size_t bo = (size_t)l * D;
        const int p0 = 2 * l, p1 = 2 * l + 1;

        GemmBatch gb;
        // pass 0: user->item (q/v from user, k from item)
        gb.X[0] = xbu; gb.W[0] = Mtb + p0 * D * D; gb.bias[0] = cb + p0 * D;    gb.C[0] = qv0;       gb.N[0] = NU; gb.cs[0] = QVS;
        gb.X[1] = xbi; gb.W[1] = Kb + p0 * D * D;  gb.bias[1] = k_b_item + bo; gb.C[1] = kb0;       gb.N[1] = NI; gb.cs[1] = D;
        gb.X[2] = xbu; gb.W[2] = Vb + p0 * D * D;  gb.bias[2] = v_b_user + bo; gb.C[2] = qv0 + 128; gb.N[2] = NU; gb.cs[2] = QVS;
        // pass 1: item->user (q/v from item, k from user)
        gb.X[3] = xbi; gb.W[3] = Mtb + p1 * D * D; gb.bias[3] = cb + p1 * D;    gb.C[3] = qv1;       gb.N[3] = NI; gb.cs[3] = QVS;
        gb.X[4] = xbu; gb.W[4] = Kb + p1 * D * D;  gb.bias[4] = k_b_user + bo; gb.C[4] = kb1;       gb.N[4] = NU; gb.cs[4] = D;
        gb.X[5] = xbi; gb.W[5] = Vb + p1 * D * D;  gb.bias[5] = v_b_item + bo; gb.C[5] = qv1 + 128; gb.N[5] = NI; gb.cs[5] = QVS;
        gemm_batch<<<dim3((maxN + 127) / 128, 6), 256, GEMM_SMEM>>>(gb);

        EdgeBatch eb;
        eb.qv[0] = qv0; eb.k[0] = kb0;
        eb.off[0] = off_ui; eb.csrc[0] = src_ui_c; eb.agg[0] = agg0; eb.n[0] = NI;
        eb.qv[1] = qv1; eb.k[1] = kb1;
        eb.off[1] = off_iu; eb.csrc[1] = src_iu_c; eb.agg[1] = agg1; eb.n[1] = NU;
        eb.psum = psum + 2 * l;
        fused_edge_batch<<<dim3(1024, 2), 256>>>(eb);

        AxpyBatch ab;
        ab.xin[0] = in_u; ab.agg[0] = agg1; ab.gsum[0] = psum + p1; ab.out[0] = out_u;
        ab.outb[0] = (l == 0) ? xbu : (__nv_bfloat16*)nullptr; ab.n4[0] = NU * D / 4;
        ab.xin[1] = in_i; ab.agg[1] = agg0; ab.gsum[1] = psum + p0; ab.out[1] = out_i;
        ab.outb[1] = (l == 0) ? xbi : (__nv_bfloat16*)nullptr; ab.n4[1] = NI * D / 4;
        axpy_batch<<<dim3((maxN * D / 4 + 255) / 256, 2), 256>>>(ab);
    }
}